// round 4
// baseline (speedup 1.0000x reference)
#include <cuda_runtime.h>
#include <cuda_bf16.h>
#include <cstdint>
#include <cstddef>

// Problem constants
#define TT   2048      // sequence length
#define EE   300       // embedding dim
#define HH   512       // hidden dim

// ---------------- device scratch (allocation-free rule: __device__ globals) -------
__device__ float g_gx[(size_t)4 * TT * 2048];   // [dir*2+sent][t][4H]  (64 MB)
__device__ float g_h[2][2][2][HH];              // [parity][dir][sent][H] (head reads [0])

__device__ __forceinline__ float sigf(float x) { return 1.f / (1.f + expf(-x)); }

__device__ __forceinline__ uint32_t smem_u32(const void* p) {
    uint32_t a;
    asm("{ .reg .u64 t; cvta.to.shared.u64 t, %1; cvt.u32.u64 %0, t; }" : "=r"(a) : "l"(p));
    return a;
}
__device__ __forceinline__ uint32_t mapa_u32(uint32_t addr, uint32_t rank) {
    uint32_t r;
    asm("mapa.shared::cluster.u32 %0, %1, %2;" : "=r"(r) : "r"(addr), "r"(rank));
    return r;
}
__device__ __forceinline__ void fma2(unsigned long long& acc,
                                     unsigned long long a, unsigned long long b) {
    asm("fma.rn.f32x2 %0, %1, %2, %0;" : "+l"(acc) : "l"(a), "l"(b));
}
__device__ __forceinline__ float acc2_sum(unsigned long long acc) {
    float lo, hi;
    asm("mov.b64 {%0, %1}, %2;" : "=f"(lo), "=f"(hi) : "l"(acc));
    return lo + hi;
}

#define MBAR_INIT(addr, cnt) \
    asm volatile("mbarrier.init.shared.b64 [%0], %1;" :: "r"(addr), "r"(cnt) : "memory")
#define MBAR_EXPECT_TX(addr, tx) \
    asm volatile("mbarrier.arrive.expect_tx.shared.b64 _, [%0], %1;" :: "r"(addr), "r"(tx) : "memory")
#define MBAR_WAIT_PARITY(addr, ph) do {                                              \
    uint32_t _m = (addr), _p = (ph), _d;                                             \
    asm volatile("{\n\t.reg .pred p;\n\t"                                            \
        "mbarrier.try_wait.parity.acquire.cta.shared::cta.b64 p, [%1], %2;\n\t"      \
        "selp.b32 %0, 1, 0, p;\n\t}"                                                 \
        : "=r"(_d) : "r"(_m), "r"(_p) : "memory");                                   \
    if (!_d) {                                                                        \
        asm volatile("{\n\t.reg .pred P1;\n\t"                                       \
            "WL_%=:\n\t"                                                              \
            "mbarrier.try_wait.parity.acquire.cta.shared::cta.b64 P1, [%0], %1, 0x989680;\n\t" \
            "@P1 bra.uni WD_%=;\n\t"                                                  \
            "bra.uni WL_%=;\n\t"                                                      \
            "WD_%=:\n\t}"                                                             \
            :: "r"(_m), "r"(_p) : "memory");                                          \
    }                                                                                 \
} while (0)

// ---------------- phase 1: gx = emb[sent] @ w_ih^T + (b_ih + b_hh) ----------------
__global__ void gemm_gx_kernel(const int* __restrict__ sA, const int* __restrict__ sB,
                               const float* __restrict__ emb,
                               const float* __restrict__ w_ih,
                               const float* __restrict__ b_ih,
                               const float* __restrict__ b_hh)
{
    const int t0 = blockIdx.x * 64;
    const int r0 = blockIdx.y * 64;
    const int s  = blockIdx.z;
    const int* sent = s ? sB : sA;
    const int d = r0 >> 11;

    __shared__ float As[32][65];
    __shared__ float Bs[32][65];
    __shared__ int   toks[64];

    const int tid = threadIdx.x;
    const int ty = tid >> 4, tx = tid & 15;

    if (tid < 64) toks[tid] = sent[t0 + tid];
    __syncthreads();

    float acc[4][4] = {};

    for (int k0 = 0; k0 < EE; k0 += 32) {
#pragma unroll
        for (int m = 0; m < 8; ++m) {
            int idx = tid + m * 256;
            int tt = idx >> 5, kk = idx & 31;
            int k = k0 + kk;
            As[kk][tt] = (k < EE) ? emb[(size_t)toks[tt] * EE + k] : 0.f;
        }
#pragma unroll
        for (int m = 0; m < 8; ++m) {
            int idx = tid + m * 256;
            int rr = idx >> 5, kk = idx & 31;
            int k = k0 + kk;
            Bs[kk][rr] = (k < EE) ? w_ih[(size_t)(r0 + rr) * EE + k] : 0.f;
        }
        __syncthreads();
#pragma unroll
        for (int kk = 0; kk < 32; ++kk) {
            float a0 = As[kk][ty * 4 + 0], a1 = As[kk][ty * 4 + 1];
            float a2 = As[kk][ty * 4 + 2], a3 = As[kk][ty * 4 + 3];
            float b0 = Bs[kk][tx * 4 + 0], b1 = Bs[kk][tx * 4 + 1];
            float b2 = Bs[kk][tx * 4 + 2], b3 = Bs[kk][tx * 4 + 3];
            acc[0][0] += a0 * b0; acc[0][1] += a0 * b1; acc[0][2] += a0 * b2; acc[0][3] += a0 * b3;
            acc[1][0] += a1 * b0; acc[1][1] += a1 * b1; acc[1][2] += a1 * b2; acc[1][3] += a1 * b3;
            acc[2][0] += a2 * b0; acc[2][1] += a2 * b1; acc[2][2] += a2 * b2; acc[2][3] += a2 * b3;
            acc[3][0] += a3 * b0; acc[3][1] += a3 * b1; acc[3][2] += a3 * b2; acc[3][3] += a3 * b3;
        }
        __syncthreads();
    }

#pragma unroll
    for (int i = 0; i < 4; ++i) {
        int t = t0 + ty * 4 + i;
        int tstore = d ? (TT - 1 - t) : t;
        size_t rowbase = (((size_t)(d * 2 + s)) * TT + tstore) * 2048;
#pragma unroll
        for (int j = 0; j < 4; ++j) {
            int r = r0 + tx * 4 + j;
            g_gx[rowbase + (r & 2047)] = acc[i][j] + b_ih[r] + b_hh[r];
        }
    }
}

// ---------------- phase 2: persistent cluster LSTM with DSMEM h-exchange ----------
// 2 clusters (one per direction) x CSZ CTAs x 512 threads.
// CTA `rank` owns units [rank*UPC, (rank+1)*UPC) for BOTH sentences.
// Per step: matvec (FFMA2) -> pointwise -> bulk-copy own h slice into all peers'
// h buffer + complete_tx on their mbarrier -> try_wait own mbarrier.
template <int CSZ>
__global__ void __launch_bounds__(512, 1)
lstm_cluster_kernel(const float* __restrict__ w_hh)
{
    constexpr int UPC   = HH / CSZ;      // units per CTA
    constexpr int ROWS  = 4 * UPC;       // gate-rows per CTA
    constexpr int NW    = 16;
    constexpr int RPW   = ROWS / NW;     // rows per warp
    constexpr int CHUNK = UPC * 4;       // bytes per (sentence) slice
    constexpr uint32_t TX_TOTAL = 2 * HH * 4;  // full h for both sentences = 4096 B

    __shared__ float h_s[2][2 * HH];                     // [buf][sent*HH + k]
    __shared__ float gates_s[2][ROWS];                   // [sent][row]
    __shared__ float stage[2 * UPC];                     // [sent*UPC + u] outgoing h
    __shared__ alignas(8) unsigned long long s_bar[2];   // ping-pong mbarriers

    const int tid  = threadIdx.x;
    const int lane = tid & 31;
    const int wid  = tid >> 5;
    const int dir  = blockIdx.x / CSZ;
    const int rank = blockIdx.x % CSZ;
    const int ku   = rank * UPC;

    // init: zero h buffer 0, init barriers
    for (int i = tid; i < 2 * HH; i += 512) h_s[0][i] = 0.f;
    if (tid == 0) {
        MBAR_INIT(smem_u32(&s_bar[0]), 1);
        MBAR_INIT(smem_u32(&s_bar[1]), 1);
    }
    __syncthreads();
    // make peers' barrier init visible before any remote complete_tx (one-time)
    asm volatile("barrier.cluster.arrive.aligned;" ::: "memory");
    asm volatile("barrier.cluster.wait.aligned;"   ::: "memory");

    const uint32_t bar_a[2] = { smem_u32(&s_bar[0]), smem_u32(&s_bar[1]) };
    const uint32_t hbuf_a[2] = { smem_u32(&h_s[0][0]), smem_u32(&h_s[1][0]) };
    const uint32_t stage_a = smem_u32(&stage[0]);

    // weight rows for this warp: rows r = wid*RPW + j, gate = r/UPC, unit = ku + r%UPC
    const float* wbase = w_hh + (size_t)dir * 2048 * HH;
    const int r_first = wid * RPW;
    const float* wrow0 = wbase + ((size_t)(r_first / UPC) * HH + ku + (r_first % UPC)) * HH;
    // (RPW consecutive rows of a warp stay within one gate block since RPW divides UPC)

    // pointwise-update identities (threads 0..2*UPC-1)
    const int uu = tid >> 1;
    const int ss = tid & 1;
    const float* pgx = g_gx + ((size_t)(dir * 2 + ss) * TT) * 2048 + (ku + uu);
    float c_reg = 0.f;

    for (int t = 0; t < TT; ++t) {
        const int rb = t & 1;            // h buffer to read
        const int wb = (t + 1) & 1;      // h buffer peers will fill
        const int bi = t & 1;            // barrier index for this step's exchange
        const int ph = (t >> 1) & 1;     // phase parity of that barrier

        // post expected tx for this step's incoming h (arrival count 1 comes with it)
        if (tid == 0) MBAR_EXPECT_TX(bar_a[bi], TX_TOTAL);

        // prefetch gx for the pointwise phase
        float gxv[4];
        if (tid < 2 * UPC) {
            const float* px = pgx + (size_t)t * 2048;
#pragma unroll
            for (int g = 0; g < 4; ++g) gxv[g] = __ldg(px + g * HH);
        }

        // ---- matvec with packed f32x2 FMAs ----
        const ulonglong2* hA2 = reinterpret_cast<const ulonglong2*>(&h_s[rb][0]);
        const ulonglong2* hB2 = reinterpret_cast<const ulonglong2*>(&h_s[rb][HH]);
        ulonglong2 ha[4], hb[4];
#pragma unroll
        for (int i = 0; i < 4; ++i) {
            ha[i] = hA2[lane + 32 * i];
            hb[i] = hB2[lane + 32 * i];
        }
        unsigned long long aA[RPW], aB[RPW];
#pragma unroll
        for (int j = 0; j < RPW; ++j) { aA[j] = 0ull; aB[j] = 0ull; }
#pragma unroll
        for (int j = 0; j < RPW; ++j) {
            const ulonglong2* wr = reinterpret_cast<const ulonglong2*>(wrow0 + (size_t)j * HH);
#pragma unroll
            for (int i = 0; i < 4; ++i) {
                ulonglong2 wv = wr[lane + 32 * i];
                fma2(aA[j], wv.x, ha[i].x);
                fma2(aA[j], wv.y, ha[i].y);
                fma2(aB[j], wv.x, hb[i].x);
                fma2(aB[j], wv.y, hb[i].y);
            }
        }
        float rA[RPW], rB[RPW];
#pragma unroll
        for (int j = 0; j < RPW; ++j) { rA[j] = acc2_sum(aA[j]); rB[j] = acc2_sum(aB[j]); }
#pragma unroll
        for (int off = 16; off; off >>= 1) {
#pragma unroll
            for (int j = 0; j < RPW; ++j) {
                rA[j] += __shfl_xor_sync(0xffffffffu, rA[j], off);
                rB[j] += __shfl_xor_sync(0xffffffffu, rB[j], off);
            }
        }
        if (lane == 0) {
#pragma unroll
            for (int j = 0; j < RPW; ++j) {
                gates_s[0][r_first + j] = rA[j];
                gates_s[1][r_first + j] = rB[j];
            }
        }
        __syncthreads();

        // ---- pointwise cell update into staging ----
        if (tid < 2 * UPC) {
            float g0 = gates_s[ss][0 * UPC + uu] + gxv[0];
            float g1 = gates_s[ss][1 * UPC + uu] + gxv[1];
            float g2 = gates_s[ss][2 * UPC + uu] + gxv[2];
            float g3 = gates_s[ss][3 * UPC + uu] + gxv[3];
            c_reg = sigf(g1) * c_reg + sigf(g0) * tanhf(g2);
            float hv = sigf(g3) * tanhf(c_reg);
            stage[ss * UPC + uu] = hv;
            if (t == TT - 1) g_h[0][dir][ss][ku + uu] = hv;
        }
        __syncthreads();

        // ---- ship own slice to all cluster CTAs (incl. self) via DSMEM bulk copy ----
        if (wid == 0 && lane < 2 * CSZ) {
            asm volatile("fence.proxy.async.shared::cta;" ::: "memory");
            const uint32_t peer = (uint32_t)(lane >> 1);
            const uint32_t c    = (uint32_t)(lane & 1);       // sentence chunk
            uint32_t src  = stage_a + c * CHUNK;
            uint32_t ldst = hbuf_a[wb] + (c * HH + ku) * 4;   // my slot offset
            uint32_t rdst = mapa_u32(ldst, peer);
            uint32_t rbar = mapa_u32(bar_a[bi], peer);
            asm volatile(
                "cp.async.bulk.shared::cluster.shared::cta.mbarrier::complete_tx::bytes "
                "[%0], [%1], %2, [%3];"
                :: "r"(rdst), "r"(src), "n"(CHUNK), "r"(rbar) : "memory");
        }

        // ---- wait for the full new h (all 2*HH floats) to land ----
        MBAR_WAIT_PARITY(bar_a[bi], (uint32_t)ph);
        __syncthreads();
    }
}

// ---------------- phase 3: bi-mix + double linear + tanh + out + sigmoid ----------
__global__ void head_kernel(const float* __restrict__ bi_w, const float* __restrict__ bi_b,
                            const float* __restrict__ blA, const float* __restrict__ blB,
                            const float* __restrict__ bl_b,
                            const float* __restrict__ out_w, const float* __restrict__ out_b,
                            float* __restrict__ out)
{
    __shared__ float hA[HH], hB[HH];
    __shared__ float red[16];
    const int j = threadIdx.x;   // 512 threads
    const float w0 = bi_w[0], w1 = bi_w[1], bb = bi_b[0];

    hA[j] = w0 * g_h[0][0][0][j] + w1 * g_h[0][1][0][j] + bb;
    hB[j] = w0 * g_h[0][0][1][j] + w1 * g_h[0][1][1][j] + bb;
    __syncthreads();

    float acc = bl_b[j];
#pragma unroll 4
    for (int i = 0; i < HH; ++i)
        acc += hA[i] * blA[(size_t)i * HH + j] + hB[i] * blB[(size_t)i * HH + j];

    float v = tanhf(acc) * out_w[j];
#pragma unroll
    for (int off = 16; off; off >>= 1) v += __shfl_xor_sync(0xffffffffu, v, off);
    if ((j & 31) == 0) red[j >> 5] = v;
    __syncthreads();
    if (j < 16) {
        float r = red[j];
#pragma unroll
        for (int off = 8; off; off >>= 1) r += __shfl_xor_sync(0x0000ffffu, r, off);
        if (j == 0) out[0] = 1.f / (1.f + expf(-(r + out_b[0])));
    }
}

// ---------------- launch ----------------------------------------------------------
extern "C" void kernel_launch(void* const* d_in, const int* in_sizes, int n_in,
                              void* d_out, int out_size)
{
    (void)in_sizes; (void)n_in; (void)out_size;
    const int*   sentA = (const int*)d_in[0];
    const int*   sentB = (const int*)d_in[1];
    const float* emb   = (const float*)d_in[3];
    const float* w_ih  = (const float*)d_in[4];
    const float* w_hh  = (const float*)d_in[5];
    const float* b_ih  = (const float*)d_in[6];
    const float* b_hh  = (const float*)d_in[7];
    const float* bi_w  = (const float*)d_in[8];
    const float* bi_b  = (const float*)d_in[9];
    const float* blA   = (const float*)d_in[10];
    const float* blB   = (const float*)d_in[11];
    const float* bl_b  = (const float*)d_in[12];
    const float* out_w = (const float*)d_in[13];
    const float* out_b = (const float*)d_in[14];
    float* out = (float*)d_out;

    gemm_gx_kernel<<<dim3(32, 64, 2), 256>>>(sentA, sentB, emb, w_ih, b_ih, b_hh);

    cudaFuncSetAttribute(lstm_cluster_kernel<16>,
                         cudaFuncAttributeNonPortableClusterSizeAllowed, 1);

    cudaLaunchConfig_t cfg = {};
    cfg.blockDim = dim3(512, 1, 1);
    cfg.dynamicSmemBytes = 0;
    cfg.stream = 0;
    cudaLaunchAttribute attr[1];
    attr[0].id = cudaLaunchAttributeClusterDimension;
    cfg.attrs = attr;
    cfg.numAttrs = 1;

    cfg.gridDim = dim3(2 * 16, 1, 1);
    attr[0].val.clusterDim.x = 16; attr[0].val.clusterDim.y = 1; attr[0].val.clusterDim.z = 1;

    int nclusters = 0;
    cudaError_t e = cudaOccupancyMaxActiveClusters(&nclusters, lstm_cluster_kernel<16>, &cfg);
    if (e == cudaSuccess && nclusters >= 1) {
        cudaLaunchKernelEx(&cfg, lstm_cluster_kernel<16>, w_hh);
    } else {
        (void)cudaGetLastError();
        cfg.gridDim = dim3(2 * 8, 1, 1);
        attr[0].val.clusterDim.x = 8;
        cudaLaunchKernelEx(&cfg, lstm_cluster_kernel<8>, w_hh);
    }

    head_kernel<<<1, 512>>>(bi_w, bi_b, blA, blB, bl_b, out_w, out_b, out);
}

// round 5
// speedup vs baseline: 1.2723x; 1.2723x over previous
#include <cuda_runtime.h>
#include <cuda_bf16.h>
#include <cstdint>
#include <cstddef>

// Problem constants
#define TT   2048      // sequence length
#define EE   300       // embedding dim
#define HH   512       // hidden dim

// ---------------- device scratch (allocation-free rule: __device__ globals) -------
__device__ float g_gx[(size_t)4 * TT * 2048];   // [dir*2+sent][t][4H]  (64 MB)
__device__ float g_h[2][2][2][HH];              // [parity][dir][sent][H] (head reads [0])

__device__ __forceinline__ float sigf(float x) { return 1.f / (1.f + expf(-x)); }

__device__ __forceinline__ uint32_t smem_u32(const void* p) {
    uint32_t a;
    asm("{ .reg .u64 t; cvta.to.shared.u64 t, %1; cvt.u32.u64 %0, t; }" : "=r"(a) : "l"(p));
    return a;
}
__device__ __forceinline__ uint32_t mapa_u32(uint32_t addr, uint32_t rank) {
    uint32_t r;
    asm("mapa.shared::cluster.u32 %0, %1, %2;" : "=r"(r) : "r"(addr), "r"(rank));
    return r;
}
__device__ __forceinline__ void fma2(unsigned long long& acc,
                                     unsigned long long a, unsigned long long b) {
    asm("fma.rn.f32x2 %0, %1, %2, %0;" : "+l"(acc) : "l"(a), "l"(b));
}
__device__ __forceinline__ float acc2_sum(unsigned long long acc) {
    float lo, hi;
    asm("mov.b64 {%0, %1}, %2;" : "=f"(lo), "=f"(hi) : "l"(acc));
    return lo + hi;
}

#define MBAR_INIT(addr, cnt) \
    asm volatile("mbarrier.init.shared.b64 [%0], %1;" :: "r"(addr), "r"(cnt) : "memory")
#define MBAR_EXPECT_TX(addr, tx) \
    asm volatile("mbarrier.arrive.expect_tx.shared.b64 _, [%0], %1;" :: "r"(addr), "r"(tx) : "memory")
#define MBAR_WAIT_PARITY(addr, ph) do {                                              \
    uint32_t _m = (addr), _p = (ph), _d;                                             \
    asm volatile("{\n\t.reg .pred p;\n\t"                                            \
        "mbarrier.try_wait.parity.acquire.cta.shared::cta.b64 p, [%1], %2;\n\t"      \
        "selp.b32 %0, 1, 0, p;\n\t}"                                                 \
        : "=r"(_d) : "r"(_m), "r"(_p) : "memory");                                   \
    if (!_d) {                                                                        \
        asm volatile("{\n\t.reg .pred P1;\n\t"                                       \
            "WL_%=:\n\t"                                                              \
            "mbarrier.try_wait.parity.acquire.cta.shared::cta.b64 P1, [%0], %1, 0x989680;\n\t" \
            "@P1 bra.uni WD_%=;\n\t"                                                  \
            "bra.uni WL_%=;\n\t"                                                      \
            "WD_%=:\n\t}"                                                             \
            :: "r"(_m), "r"(_p) : "memory");                                          \
    }                                                                                 \
} while (0)

// ---------------- phase 1: gx = emb[sent] @ w_ih^T + (b_ih + b_hh) ----------------
__global__ void gemm_gx_kernel(const int* __restrict__ sA, const int* __restrict__ sB,
                               const float* __restrict__ emb,
                               const float* __restrict__ w_ih,
                               const float* __restrict__ b_ih,
                               const float* __restrict__ b_hh)
{
    const int t0 = blockIdx.x * 64;
    const int r0 = blockIdx.y * 64;
    const int s  = blockIdx.z;
    const int* sent = s ? sB : sA;
    const int d = r0 >> 11;

    __shared__ float As[32][65];
    __shared__ float Bs[32][65];
    __shared__ int   toks[64];

    const int tid = threadIdx.x;
    const int ty = tid >> 4, tx = tid & 15;

    if (tid < 64) toks[tid] = sent[t0 + tid];
    __syncthreads();

    float acc[4][4] = {};

    for (int k0 = 0; k0 < EE; k0 += 32) {
#pragma unroll
        for (int m = 0; m < 8; ++m) {
            int idx = tid + m * 256;
            int tt = idx >> 5, kk = idx & 31;
            int k = k0 + kk;
            As[kk][tt] = (k < EE) ? emb[(size_t)toks[tt] * EE + k] : 0.f;
        }
#pragma unroll
        for (int m = 0; m < 8; ++m) {
            int idx = tid + m * 256;
            int rr = idx >> 5, kk = idx & 31;
            int k = k0 + kk;
            Bs[kk][rr] = (k < EE) ? w_ih[(size_t)(r0 + rr) * EE + k] : 0.f;
        }
        __syncthreads();
#pragma unroll
        for (int kk = 0; kk < 32; ++kk) {
            float a0 = As[kk][ty * 4 + 0], a1 = As[kk][ty * 4 + 1];
            float a2 = As[kk][ty * 4 + 2], a3 = As[kk][ty * 4 + 3];
            float b0 = Bs[kk][tx * 4 + 0], b1 = Bs[kk][tx * 4 + 1];
            float b2 = Bs[kk][tx * 4 + 2], b3 = Bs[kk][tx * 4 + 3];
            acc[0][0] += a0 * b0; acc[0][1] += a0 * b1; acc[0][2] += a0 * b2; acc[0][3] += a0 * b3;
            acc[1][0] += a1 * b0; acc[1][1] += a1 * b1; acc[1][2] += a1 * b2; acc[1][3] += a1 * b3;
            acc[2][0] += a2 * b0; acc[2][1] += a2 * b1; acc[2][2] += a2 * b2; acc[2][3] += a2 * b3;
            acc[3][0] += a3 * b0; acc[3][1] += a3 * b1; acc[3][2] += a3 * b2; acc[3][3] += a3 * b3;
        }
        __syncthreads();
    }

#pragma unroll
    for (int i = 0; i < 4; ++i) {
        int t = t0 + ty * 4 + i;
        int tstore = d ? (TT - 1 - t) : t;
        size_t rowbase = (((size_t)(d * 2 + s)) * TT + tstore) * 2048;
#pragma unroll
        for (int j = 0; j < 4; ++j) {
            int r = r0 + tx * 4 + j;
            g_gx[rowbase + (r & 2047)] = acc[i][j] + b_ih[r] + b_hh[r];
        }
    }
}

// ---------------- phase 2: persistent cluster LSTM, register-resident weights -----
// 2 clusters (one per direction) x CSZ CTAs x 256 threads.
// CTA `rank` owns units [rank*UPC, (rank+1)*UPC) for BOTH sentences.
// Each warp owns RPW = ROWS/8 contiguous gate-rows. The first REG_ROWS of them
// live in registers for the whole kernel (zero per-step load traffic); the rest
// stream from an L1-resident working set.
template <int CSZ>
__global__ void __launch_bounds__(256, 1)
lstm_cluster_kernel(const float* __restrict__ w_hh)
{
    constexpr int NT     = 256;
    constexpr int UPC    = HH / CSZ;       // units per CTA
    constexpr int ROWS   = 4 * UPC;        // gate-rows per CTA
    constexpr int NW     = 8;              // warps per CTA
    constexpr int RPW    = ROWS / NW;      // rows per warp (16 for CSZ=16)
    constexpr int NB     = RPW / 4;        // batches of 4 rows
    constexpr int REG_ROWS = 8;            // rows per thread kept in registers
    constexpr int CHUNK  = UPC * 4;        // bytes per sentence slice
    constexpr uint32_t TX_TOTAL = 2 * HH * 4;

    __shared__ float h_s[2][2 * HH];                     // [buf][sent*HH + k]
    __shared__ float gates_s[2][ROWS];                   // [sent][row]
    __shared__ float stage[2 * UPC];                     // outgoing h
    __shared__ alignas(8) unsigned long long s_bar[2];   // ping-pong mbarriers

    const int tid  = threadIdx.x;
    const int lane = tid & 31;
    const int wid  = tid >> 5;
    const int dir  = blockIdx.x / CSZ;
    const int rank = blockIdx.x % CSZ;
    const int ku   = rank * UPC;

    for (int i = tid; i < 2 * HH; i += NT) h_s[0][i] = 0.f;
    if (tid == 0) {
        MBAR_INIT(smem_u32(&s_bar[0]), 1);
        MBAR_INIT(smem_u32(&s_bar[1]), 1);
    }
    __syncthreads();
    asm volatile("barrier.cluster.arrive.aligned;" ::: "memory");
    asm volatile("barrier.cluster.wait.aligned;"   ::: "memory");

    const uint32_t bar_a[2]  = { smem_u32(&s_bar[0]), smem_u32(&s_bar[1]) };
    const uint32_t hbuf_a[2] = { smem_u32(&h_s[0][0]), smem_u32(&h_s[1][0]) };
    const uint32_t stage_a   = smem_u32(&stage[0]);

    // warp's first row: rows [r_first, r_first+RPW) are contiguous in memory
    // because RPW divides UPC (gate = r/UPC constant within the span).
    const float* wbase = w_hh + (size_t)dir * 2048 * HH;
    const int r_first = wid * RPW;
    const float* wrow0 = wbase + ((size_t)(r_first / UPC) * HH + ku + (r_first % UPC)) * HH;

    // ---- preload REG_ROWS rows into registers (persist across all 2048 steps) ----
    ulonglong2 wreg[REG_ROWS][4];
#pragma unroll
    for (int j = 0; j < REG_ROWS; ++j) {
        const ulonglong2* wr = reinterpret_cast<const ulonglong2*>(wrow0 + (size_t)j * HH);
#pragma unroll
        for (int i = 0; i < 4; ++i) wreg[j][i] = wr[lane + 32 * i];
    }

    // pointwise-update identities (threads 0..2*UPC-1)
    const int uu = tid >> 1;
    const int ss = tid & 1;
    const float* pgx = g_gx + ((size_t)(dir * 2 + ss) * TT) * 2048 + (ku + uu);
    float c_reg = 0.f;

    for (int t = 0; t < TT; ++t) {
        const int rb = t & 1;
        const int wb = (t + 1) & 1;
        const int bi = t & 1;
        const int ph = (t >> 1) & 1;

        if (tid == 0) MBAR_EXPECT_TX(bar_a[bi], TX_TOTAL);

        float gxv[4];
        if (tid < 2 * UPC) {
            const float* px = pgx + (size_t)t * 2048;
#pragma unroll
            for (int g = 0; g < 4; ++g) gxv[g] = __ldg(px + g * HH);
        }

        // ---- h into registers ----
        const ulonglong2* hA2 = reinterpret_cast<const ulonglong2*>(&h_s[rb][0]);
        const ulonglong2* hB2 = reinterpret_cast<const ulonglong2*>(&h_s[rb][HH]);
        ulonglong2 ha[4], hb[4];
#pragma unroll
        for (int i = 0; i < 4; ++i) {
            ha[i] = hA2[lane + 32 * i];
            hb[i] = hB2[lane + 32 * i];
        }

        // ---- matvec in batches of 4 rows ----
#pragma unroll
        for (int b = 0; b < NB; ++b) {
            unsigned long long aA[4] = {0ull, 0ull, 0ull, 0ull};
            unsigned long long aB[4] = {0ull, 0ull, 0ull, 0ull};
            if (4 * b + 4 <= REG_ROWS) {
                // register-resident rows
#pragma unroll
                for (int r = 0; r < 4; ++r) {
#pragma unroll
                    for (int i = 0; i < 4; ++i) {
                        ulonglong2 wv = wreg[4 * b + r][i];
                        fma2(aA[r], wv.x, ha[i].x);
                        fma2(aA[r], wv.y, ha[i].y);
                        fma2(aB[r], wv.x, hb[i].x);
                        fma2(aB[r], wv.y, hb[i].y);
                    }
                }
            } else {
                // streamed rows (L1-resident), 2 rows at a time to bound registers
#pragma unroll
                for (int rp = 0; rp < 2; ++rp) {
                    ulonglong2 wt[2][4];
#pragma unroll
                    for (int r = 0; r < 2; ++r) {
                        const ulonglong2* wr = reinterpret_cast<const ulonglong2*>(
                            wrow0 + (size_t)(4 * b + 2 * rp + r) * HH);
#pragma unroll
                        for (int i = 0; i < 4; ++i) wt[r][i] = wr[lane + 32 * i];
                    }
#pragma unroll
                    for (int r = 0; r < 2; ++r) {
#pragma unroll
                        for (int i = 0; i < 4; ++i) {
                            fma2(aA[2 * rp + r], wt[r][i].x, ha[i].x);
                            fma2(aA[2 * rp + r], wt[r][i].y, ha[i].y);
                            fma2(aB[2 * rp + r], wt[r][i].x, hb[i].x);
                            fma2(aB[2 * rp + r], wt[r][i].y, hb[i].y);
                        }
                    }
                }
            }
            float rA[4], rB[4];
#pragma unroll
            for (int r = 0; r < 4; ++r) { rA[r] = acc2_sum(aA[r]); rB[r] = acc2_sum(aB[r]); }
#pragma unroll
            for (int off = 16; off; off >>= 1) {
#pragma unroll
                for (int r = 0; r < 4; ++r) {
                    rA[r] += __shfl_xor_sync(0xffffffffu, rA[r], off);
                    rB[r] += __shfl_xor_sync(0xffffffffu, rB[r], off);
                }
            }
            if (lane == 0) {
#pragma unroll
                for (int r = 0; r < 4; ++r) {
                    gates_s[0][r_first + 4 * b + r] = rA[r];
                    gates_s[1][r_first + 4 * b + r] = rB[r];
                }
            }
        }
        __syncthreads();

        // ---- pointwise cell update into staging ----
        if (tid < 2 * UPC) {
            float g0 = gates_s[ss][0 * UPC + uu] + gxv[0];
            float g1 = gates_s[ss][1 * UPC + uu] + gxv[1];
            float g2 = gates_s[ss][2 * UPC + uu] + gxv[2];
            float g3 = gates_s[ss][3 * UPC + uu] + gxv[3];
            c_reg = sigf(g1) * c_reg + sigf(g0) * tanhf(g2);
            float hv = sigf(g3) * tanhf(c_reg);
            stage[ss * UPC + uu] = hv;
            if (t == TT - 1) g_h[0][dir][ss][ku + uu] = hv;
        }
        __syncthreads();

        // ---- ship own slice to all cluster CTAs (incl. self) via DSMEM bulk copy ----
        if (wid == 0 && lane < 2 * CSZ) {
            asm volatile("fence.proxy.async.shared::cta;" ::: "memory");
            const uint32_t peer = (uint32_t)(lane >> 1);
            const uint32_t c    = (uint32_t)(lane & 1);
            uint32_t src  = stage_a + c * CHUNK;
            uint32_t ldst = hbuf_a[wb] + (c * HH + ku) * 4;
            uint32_t rdst = mapa_u32(ldst, peer);
            uint32_t rbar = mapa_u32(bar_a[bi], peer);
            asm volatile(
                "cp.async.bulk.shared::cluster.shared::cta.mbarrier::complete_tx::bytes "
                "[%0], [%1], %2, [%3];"
                :: "r"(rdst), "r"(src), "n"(CHUNK), "r"(rbar) : "memory");
        }

        MBAR_WAIT_PARITY(bar_a[bi], (uint32_t)ph);
        __syncthreads();
    }
}

// ---------------- phase 3: bi-mix + double linear + tanh + out + sigmoid ----------
__global__ void head_kernel(const float* __restrict__ bi_w, const float* __restrict__ bi_b,
                            const float* __restrict__ blA, const float* __restrict__ blB,
                            const float* __restrict__ bl_b,
                            const float* __restrict__ out_w, const float* __restrict__ out_b,
                            float* __restrict__ out)
{
    __shared__ float hA[HH], hB[HH];
    __shared__ float red[16];
    const int j = threadIdx.x;   // 512 threads
    const float w0 = bi_w[0], w1 = bi_w[1], bb = bi_b[0];

    hA[j] = w0 * g_h[0][0][0][j] + w1 * g_h[0][1][0][j] + bb;
    hB[j] = w0 * g_h[0][0][1][j] + w1 * g_h[0][1][1][j] + bb;
    __syncthreads();

    float acc = bl_b[j];
#pragma unroll 4
    for (int i = 0; i < HH; ++i)
        acc += hA[i] * blA[(size_t)i * HH + j] + hB[i] * blB[(size_t)i * HH + j];

    float v = tanhf(acc) * out_w[j];
#pragma unroll
    for (int off = 16; off; off >>= 1) v += __shfl_xor_sync(0xffffffffu, v, off);
    if ((j & 31) == 0) red[j >> 5] = v;
    __syncthreads();
    if (j < 16) {
        float r = red[j];
#pragma unroll
        for (int off = 8; off; off >>= 1) r += __shfl_xor_sync(0x0000ffffu, r, off);
        if (j == 0) out[0] = 1.f / (1.f + expf(-(r + out_b[0])));
    }
}

// ---------------- launch ----------------------------------------------------------
extern "C" void kernel_launch(void* const* d_in, const int* in_sizes, int n_in,
                              void* d_out, int out_size)
{
    (void)in_sizes; (void)n_in; (void)out_size;
    const int*   sentA = (const int*)d_in[0];
    const int*   sentB = (const int*)d_in[1];
    const float* emb   = (const float*)d_in[3];
    const float* w_ih  = (const float*)d_in[4];
    const float* w_hh  = (const float*)d_in[5];
    const float* b_ih  = (const float*)d_in[6];
    const float* b_hh  = (const float*)d_in[7];
    const float* bi_w  = (const float*)d_in[8];
    const float* bi_b  = (const float*)d_in[9];
    const float* blA   = (const float*)d_in[10];
    const float* blB   = (const float*)d_in[11];
    const float* bl_b  = (const float*)d_in[12];
    const float* out_w = (const float*)d_in[13];
    const float* out_b = (const float*)d_in[14];
    float* out = (float*)d_out;

    gemm_gx_kernel<<<dim3(32, 64, 2), 256>>>(sentA, sentB, emb, w_ih, b_ih, b_hh);

    cudaFuncSetAttribute(lstm_cluster_kernel<16>,
                         cudaFuncAttributeNonPortableClusterSizeAllowed, 1);

    cudaLaunchConfig_t cfg = {};
    cfg.blockDim = dim3(256, 1, 1);
    cfg.dynamicSmemBytes = 0;
    cfg.stream = 0;
    cudaLaunchAttribute attr[1];
    attr[0].id = cudaLaunchAttributeClusterDimension;
    cfg.attrs = attr;
    cfg.numAttrs = 1;

    cfg.gridDim = dim3(2 * 16, 1, 1);
    attr[0].val.clusterDim.x = 16; attr[0].val.clusterDim.y = 1; attr[0].val.clusterDim.z = 1;

    int nclusters = 0;
    cudaError_t e = cudaOccupancyMaxActiveClusters(&nclusters, lstm_cluster_kernel<16>, &cfg);
    if (e == cudaSuccess && nclusters >= 1) {
        cudaLaunchKernelEx(&cfg, lstm_cluster_kernel<16>, w_hh);
    } else {
        (void)cudaGetLastError();
        cfg.gridDim = dim3(2 * 8, 1, 1);
        attr[0].val.clusterDim.x = 8;
        cudaLaunchKernelEx(&cfg, lstm_cluster_kernel<8>, w_hh);
    }

    head_kernel<<<1, 512>>>(bi_w, bi_b, blA, blB, bl_b, out_w, out_b, out);
}

// round 7
// speedup vs baseline: 1.3740x; 1.0799x over previous
#include <cuda_runtime.h>
#include <cuda_bf16.h>
#include <cstdint>
#include <cstddef>

// Problem constants
#define TT   2048      // sequence length
#define EE   300       // embedding dim
#define HH   512       // hidden dim

// ---------------- device scratch (allocation-free rule: __device__ globals) -------
__device__ float g_gx[(size_t)4 * TT * 2048];   // [dir*2+sent][t][4H]  (64 MB)
__device__ float g_h[2][2][2][HH];              // [parity][dir][sent][H] (head reads [0])

__device__ __forceinline__ float sigf(float x) { return 1.f / (1.f + expf(-x)); }

__device__ __forceinline__ uint32_t smem_u32(const void* p) {
    uint32_t a;
    asm("{ .reg .u64 t; cvta.to.shared.u64 t, %1; cvt.u32.u64 %0, t; }" : "=r"(a) : "l"(p));
    return a;
}
__device__ __forceinline__ uint32_t mapa_u32(uint32_t addr, uint32_t rank) {
    uint32_t r;
    asm("mapa.shared::cluster.u32 %0, %1, %2;" : "=r"(r) : "r"(addr), "r"(rank));
    return r;
}
__device__ __forceinline__ void fma2(unsigned long long& acc,
                                     unsigned long long a, unsigned long long b) {
    asm("fma.rn.f32x2 %0, %1, %2, %0;" : "+l"(acc) : "l"(a), "l"(b));
}
__device__ __forceinline__ float acc2_sum(unsigned long long acc) {
    float lo, hi;
    asm("mov.b64 {%0, %1}, %2;" : "=f"(lo), "=f"(hi) : "l"(acc));
    return lo + hi;
}
__device__ __forceinline__ unsigned long long pack2(float a, float b) {
    unsigned long long r;
    asm("mov.b64 %0, {%1, %2};" : "=l"(r) : "f"(a), "f"(b));
    return r;
}
__device__ __forceinline__ void unpack2(unsigned long long v, float& a, float& b) {
    asm("mov.b64 {%0, %1}, %2;" : "=f"(a), "=f"(b) : "l"(v));
}
__device__ __forceinline__ void add2(unsigned long long& acc, unsigned long long v) {
    asm("add.rn.f32x2 %0, %0, %1;" : "+l"(acc) : "l"(v));
}
// warp-sum of a packed (A,B) pair: 5 shuffles + 5 f32x2 adds
__device__ __forceinline__ unsigned long long warp_sum2(unsigned long long v) {
#pragma unroll
    for (int off = 16; off; off >>= 1) {
        unsigned long long o = __shfl_xor_sync(0xffffffffu, v, off);
        add2(v, o);
    }
    return v;
}

#define MBAR_INIT(addr, cnt) \
    asm volatile("mbarrier.init.shared.b64 [%0], %1;" :: "r"(addr), "r"(cnt) : "memory")
#define MBAR_EXPECT_TX(addr, tx) \
    asm volatile("mbarrier.arrive.expect_tx.shared.b64 _, [%0], %1;" :: "r"(addr), "r"(tx) : "memory")
#define MBAR_WAIT_PARITY(addr, ph) do {                                              \
    uint32_t _m = (addr), _p = (ph), _d;                                             \
    asm volatile("{\n\t.reg .pred p;\n\t"                                            \
        "mbarrier.try_wait.parity.acquire.cta.shared::cta.b64 p, [%1], %2;\n\t"      \
        "selp.b32 %0, 1, 0, p;\n\t}"                                                 \
        : "=r"(_d) : "r"(_m), "r"(_p) : "memory");                                   \
    if (!_d) {                                                                        \
        asm volatile("{\n\t.reg .pred P1;\n\t"                                       \
            "WL_%=:\n\t"                                                              \
            "mbarrier.try_wait.parity.acquire.cta.shared::cta.b64 P1, [%0], %1, 0x989680;\n\t" \
            "@P1 bra.uni WD_%=;\n\t"                                                  \
            "bra.uni WL_%=;\n\t"                                                      \
            "WD_%=:\n\t}"                                                             \
            :: "r"(_m), "r"(_p) : "memory");                                          \
    }                                                                                 \
} while (0)

// ---------------- phase 1: gx = emb[sent] @ w_ih^T + (b_ih + b_hh) ----------------
__global__ void gemm_gx_kernel(const int* __restrict__ sA, const int* __restrict__ sB,
                               const float* __restrict__ emb,
                               const float* __restrict__ w_ih,
                               const float* __restrict__ b_ih,
                               const float* __restrict__ b_hh)
{
    const int t0 = blockIdx.x * 64;
    const int r0 = blockIdx.y * 64;
    const int s  = blockIdx.z;
    const int* sent = s ? sB : sA;
    const int d = r0 >> 11;

    __shared__ float As[32][65];
    __shared__ float Bs[32][65];
    __shared__ int   toks[64];

    const int tid = threadIdx.x;
    const int ty = tid >> 4, tx = tid & 15;

    if (tid < 64) toks[tid] = sent[t0 + tid];
    __syncthreads();

    float acc[4][4] = {};

    for (int k0 = 0; k0 < EE; k0 += 32) {
#pragma unroll
        for (int m = 0; m < 8; ++m) {
            int idx = tid + m * 256;
            int tt = idx >> 5, kk = idx & 31;
            int k = k0 + kk;
            As[kk][tt] = (k < EE) ? emb[(size_t)toks[tt] * EE + k] : 0.f;
        }
#pragma unroll
        for (int m = 0; m < 8; ++m) {
            int idx = tid + m * 256;
            int rr = idx >> 5, kk = idx & 31;
            int k = k0 + kk;
            Bs[kk][rr] = (k < EE) ? w_ih[(size_t)(r0 + rr) * EE + k] : 0.f;
        }
        __syncthreads();
#pragma unroll
        for (int kk = 0; kk < 32; ++kk) {
            float a0 = As[kk][ty * 4 + 0], a1 = As[kk][ty * 4 + 1];
            float a2 = As[kk][ty * 4 + 2], a3 = As[kk][ty * 4 + 3];
            float b0 = Bs[kk][tx * 4 + 0], b1 = Bs[kk][tx * 4 + 1];
            float b2 = Bs[kk][tx * 4 + 2], b3 = Bs[kk][tx * 4 + 3];
            acc[0][0] += a0 * b0; acc[0][1] += a0 * b1; acc[0][2] += a0 * b2; acc[0][3] += a0 * b3;
            acc[1][0] += a1 * b0; acc[1][1] += a1 * b1; acc[1][2] += a1 * b2; acc[1][3] += a1 * b3;
            acc[2][0] += a2 * b0; acc[2][1] += a2 * b1; acc[2][2] += a2 * b2; acc[2][3] += a2 * b3;
            acc[3][0] += a3 * b0; acc[3][1] += a3 * b1; acc[3][2] += a3 * b2; acc[3][3] += a3 * b3;
        }
        __syncthreads();
    }

#pragma unroll
    for (int i = 0; i < 4; ++i) {
        int t = t0 + ty * 4 + i;
        int tstore = d ? (TT - 1 - t) : t;
        size_t rowbase = (((size_t)(d * 2 + s)) * TT + tstore) * 2048;
#pragma unroll
        for (int j = 0; j < 4; ++j) {
            int r = r0 + tx * 4 + j;
            g_gx[rowbase + (r & 2047)] = acc[i][j] + b_ih[r] + b_hh[r];
        }
    }
}

// ---------------- phase 2: persistent cluster LSTM ------------------------------
// 2 clusters (one per direction) x CSZ CTAs x 256 threads.
// Weight rows per warp (RPW): first 4 in registers, next 12 in SMEM (LDS-streamed
// with double-buffered prefetch), remainder (CSZ=8 fallback only) from global.
// Warp-sums via packed f32x2 shuffles. h exchanged via DSMEM bulk copy + mbarrier.
template <int CSZ>
__global__ void __launch_bounds__(256, 1)
lstm_cluster_kernel(const float* __restrict__ w_hh)
{
    constexpr int NT   = 256;
    constexpr int NW   = 8;
    constexpr int UPC  = HH / CSZ;
    constexpr int ROWS = 4 * UPC;
    constexpr int RPW  = ROWS / NW;
    constexpr int REG_ROWS  = 4;
    constexpr int SMEM_ROWS = 12;                       // rows/warp kept in SMEM
    constexpr int SMEM_PAIRS = SMEM_ROWS / 2;           // 6
    constexpr int LDG_ROWS  = RPW - REG_ROWS - SMEM_ROWS;  // 0 (CSZ16) / 16 (CSZ8)
    constexpr int LDG_PAIRS = LDG_ROWS / 2;
    constexpr int CHUNK = UPC * 4;
    constexpr uint32_t TX_TOTAL = 2 * HH * 4;

    extern __shared__ float smf[];
    float* w_sm    = smf;                               // NW*SMEM_ROWS*HH floats
    float* h_s     = w_sm + NW * SMEM_ROWS * HH;        // [2][2*HH]
    float* gates   = h_s + 4 * HH;                      // [2][ROWS]
    float* stage   = gates + 2 * ROWS;                  // [2*UPC]
    unsigned long long* s_bar = reinterpret_cast<unsigned long long*>(stage + 2 * UPC);

    const int tid  = threadIdx.x;
    const int lane = tid & 31;
    const int wid  = tid >> 5;
    const int dir  = blockIdx.x / CSZ;
    const int rank = blockIdx.x % CSZ;
    const int ku   = rank * UPC;

    for (int i = tid; i < 2 * HH; i += NT) h_s[i] = 0.f;   // h buffer 0
    if (tid == 0) {
        MBAR_INIT(smem_u32(&s_bar[0]), 1);
        MBAR_INIT(smem_u32(&s_bar[1]), 1);
    }

    // warp's contiguous row block (RPW divides UPC or equals it)
    const float* wbase = w_hh + (size_t)dir * 2048 * HH;
    const int r_first = wid * RPW;
    const float* wrow0 = wbase + ((size_t)(r_first / UPC) * HH + ku + (r_first % UPC)) * HH;

    // one-time: copy SMEM_ROWS rows (j = REG_ROWS .. REG_ROWS+SMEM_ROWS-1) to SMEM
    for (int j = 0; j < SMEM_ROWS; ++j) {
        const float4* src = reinterpret_cast<const float4*>(wrow0 + (size_t)(REG_ROWS + j) * HH);
        float4* dst = reinterpret_cast<float4*>(w_sm + (size_t)(wid * SMEM_ROWS + j) * HH);
        for (int i = lane; i < HH / 4; i += 32) dst[i] = src[i];
    }

    // one-time: REG_ROWS rows into registers
    ulonglong2 wreg[REG_ROWS][4];
#pragma unroll
    for (int j = 0; j < REG_ROWS; ++j) {
        const ulonglong2* wr = reinterpret_cast<const ulonglong2*>(wrow0 + (size_t)j * HH);
#pragma unroll
        for (int i = 0; i < 4; ++i) wreg[j][i] = wr[lane + 32 * i];
    }

    __syncthreads();
    asm volatile("barrier.cluster.arrive.aligned;" ::: "memory");
    asm volatile("barrier.cluster.wait.aligned;"   ::: "memory");

    const uint32_t bar_a[2]  = { smem_u32(&s_bar[0]), smem_u32(&s_bar[1]) };
    const uint32_t hbuf_a[2] = { smem_u32(h_s), smem_u32(h_s + 2 * HH) };
    const uint32_t stage_a   = smem_u32(stage);

    const ulonglong2* wsm2 = reinterpret_cast<const ulonglong2*>(
        w_sm + (size_t)(wid * SMEM_ROWS) * HH);

    // pointwise identities (threads 0..2*UPC-1)
    const int uu = tid >> 1;
    const int ss = tid & 1;
    const float* pgx = g_gx + ((size_t)(dir * 2 + ss) * TT) * 2048 + (ku + uu);
    float c_reg = 0.f;

    for (int t = 0; t < TT; ++t) {
        const int rb = t & 1;
        const int wb = (t + 1) & 1;
        const int bi = t & 1;
        const int ph = (t >> 1) & 1;

        if (tid == 0) MBAR_EXPECT_TX(bar_a[bi], TX_TOTAL);

        float gxv[4];
        if (tid < 2 * UPC) {
            const float* px = pgx + (size_t)t * 2048;
#pragma unroll
            for (int g = 0; g < 4; ++g) gxv[g] = __ldg(px + g * HH);
        }

        // h (both sentences) into registers
        const ulonglong2* hA2 = reinterpret_cast<const ulonglong2*>(h_s + rb * 2 * HH);
        const ulonglong2* hB2 = reinterpret_cast<const ulonglong2*>(h_s + rb * 2 * HH + HH);
        ulonglong2 ha[4], hb[4];
#pragma unroll
        for (int i = 0; i < 4; ++i) {
            ha[i] = hA2[lane + 32 * i];
            hb[i] = hB2[lane + 32 * i];
        }

        // prefetch SMEM pairs 0 and 1
        ulonglong2 buf[2][2][4];
#pragma unroll
        for (int p = 0; p < 2; ++p)
#pragma unroll
            for (int r = 0; r < 2; ++r)
#pragma unroll
                for (int i = 0; i < 4; ++i)
                    buf[p][r][i] = wsm2[(size_t)(2 * p + r) * (HH / 4) + lane + 32 * i];

        // ---- register rows (0..REG_ROWS-1) ----
        {
            unsigned long long aA[REG_ROWS], aB[REG_ROWS];
#pragma unroll
            for (int r = 0; r < REG_ROWS; ++r) { aA[r] = 0ull; aB[r] = 0ull; }
#pragma unroll
            for (int r = 0; r < REG_ROWS; ++r)
#pragma unroll
                for (int i = 0; i < 4; ++i) {
                    fma2(aA[r], wreg[r][i].x, ha[i].x);
                    fma2(aA[r], wreg[r][i].y, ha[i].y);
                    fma2(aB[r], wreg[r][i].x, hb[i].x);
                    fma2(aB[r], wreg[r][i].y, hb[i].y);
                }
#pragma unroll
            for (int r = 0; r < REG_ROWS; ++r) {
                unsigned long long v = warp_sum2(pack2(acc2_sum(aA[r]), acc2_sum(aB[r])));
                if (lane == 0) {
                    float fA, fB;
                    unpack2(v, fA, fB);
                    gates[0 * ROWS + r_first + r] = fA;
                    gates[1 * ROWS + r_first + r] = fB;
                }
            }
        }

        // ---- SMEM-streamed pairs with double-buffered prefetch ----
#pragma unroll
        for (int p = 0; p < SMEM_PAIRS; ++p) {
            unsigned long long aA[2] = {0ull, 0ull}, aB[2] = {0ull, 0ull};
#pragma unroll
            for (int r = 0; r < 2; ++r)
#pragma unroll
                for (int i = 0; i < 4; ++i) {
                    ulonglong2 wv = buf[p & 1][r][i];
                    fma2(aA[r], wv.x, ha[i].x);
                    fma2(aA[r], wv.y, ha[i].y);
                    fma2(aB[r], wv.x, hb[i].x);
                    fma2(aB[r], wv.y, hb[i].y);
                }
            if (p + 2 < SMEM_PAIRS) {
#pragma unroll
                for (int r = 0; r < 2; ++r)
#pragma unroll
                    for (int i = 0; i < 4; ++i)
                        buf[p & 1][r][i] =
                            wsm2[(size_t)(2 * (p + 2) + r) * (HH / 4) + lane + 32 * i];
            }
#pragma unroll
            for (int r = 0; r < 2; ++r) {
                unsigned long long v = warp_sum2(pack2(acc2_sum(aA[r]), acc2_sum(aB[r])));
                if (lane == 0) {
                    float fA, fB;
                    unpack2(v, fA, fB);
                    gates[0 * ROWS + r_first + REG_ROWS + 2 * p + r] = fA;
                    gates[1 * ROWS + r_first + REG_ROWS + 2 * p + r] = fB;
                }
            }
        }

        // ---- global-streamed pairs (fallback CSZ=8 only) ----
        if constexpr (LDG_PAIRS > 0) {
#pragma unroll 2
            for (int p = 0; p < LDG_PAIRS; ++p) {
                ulonglong2 wt[2][4];
#pragma unroll
                for (int r = 0; r < 2; ++r) {
                    const ulonglong2* wr = reinterpret_cast<const ulonglong2*>(
                        wrow0 + (size_t)(REG_ROWS + SMEM_ROWS + 2 * p + r) * HH);
#pragma unroll
                    for (int i = 0; i < 4; ++i) wt[r][i] = wr[lane + 32 * i];
                }
                unsigned long long aA[2] = {0ull, 0ull}, aB[2] = {0ull, 0ull};
#pragma unroll
                for (int r = 0; r < 2; ++r)
#pragma unroll
                    for (int i = 0; i < 4; ++i) {
                        fma2(aA[r], wt[r][i].x, ha[i].x);
                        fma2(aA[r], wt[r][i].y, ha[i].y);
                        fma2(aB[r], wt[r][i].x, hb[i].x);
                        fma2(aB[r], wt[r][i].y, hb[i].y);
                    }
#pragma unroll
                for (int r = 0; r < 2; ++r) {
                    unsigned long long v = warp_sum2(pack2(acc2_sum(aA[r]), acc2_sum(aB[r])));
                    if (lane == 0) {
                        float fA, fB;
                        unpack2(v, fA, fB);
                        gates[0 * ROWS + r_first + REG_ROWS + SMEM_ROWS + 2 * p + r] = fA;
                        gates[1 * ROWS + r_first + REG_ROWS + SMEM_ROWS + 2 * p + r] = fB;
                    }
                }
            }
        }
        __syncthreads();

        // ---- pointwise cell update into staging ----
        if (tid < 2 * UPC) {
            float g0 = gates[ss * ROWS + 0 * UPC + uu] + gxv[0];
            float g1 = gates[ss * ROWS + 1 * UPC + uu] + gxv[1];
            float g2 = gates[ss * ROWS + 2 * UPC + uu] + gxv[2];
            float g3 = gates[ss * ROWS + 3 * UPC + uu] + gxv[3];
            c_reg = sigf(g1) * c_reg + sigf(g0) * tanhf(g2);
            float hv = sigf(g3) * tanhf(c_reg);
            stage[ss * UPC + uu] = hv;
            if (t == TT - 1) g_h[0][dir][ss][ku + uu] = hv;
        }
        __syncthreads();

        // ---- ship own slice to all cluster CTAs (incl. self) via DSMEM bulk copy ----
        if (wid == 0 && lane < 2 * CSZ) {
            asm volatile("fence.proxy.async.shared::cta;" ::: "memory");
            const uint32_t peer = (uint32_t)(lane >> 1);
            const uint32_t c    = (uint32_t)(lane & 1);
            uint32_t src  = stage_a + c * CHUNK;
            uint32_t ldst = hbuf_a[wb] + (c * HH + ku) * 4;
            uint32_t rdst = mapa_u32(ldst, peer);
            uint32_t rbar = mapa_u32(bar_a[bi], peer);
            asm volatile(
                "cp.async.bulk.shared::cluster.shared::cta.mbarrier::complete_tx::bytes "
                "[%0], [%1], %2, [%3];"
                :: "r"(rdst), "r"(src), "n"(CHUNK), "r"(rbar) : "memory");
        }

        MBAR_WAIT_PARITY(bar_a[bi], (uint32_t)ph);
        __syncthreads();
    }
}

// ---------------- phase 3: bi-mix + double linear + tanh + out + sigmoid ----------
__global__ void head_kernel(const float* __restrict__ bi_w, const float* __restrict__ bi_b,
                            const float* __restrict__ blA, const float* __restrict__ blB,
                            const float* __restrict__ bl_b,
                            const float* __restrict__ out_w, const float* __restrict__ out_b,
                            float* __restrict__ out)
{
    __shared__ float hA[HH], hB[HH];
    __shared__ float red[16];
    const int j = threadIdx.x;   // 512 threads
    const float w0 = bi_w[0], w1 = bi_w[1], bb = bi_b[0];

    hA[j] = w0 * g_h[0][0][0][j] + w1 * g_h[0][1][0][j] + bb;
    hB[j] = w0 * g_h[0][0][1][j] + w1 * g_h[0][1][1][j] + bb;
    __syncthreads();

    float acc = bl_b[j];
#pragma unroll 4
    for (int i = 0; i < HH; ++i)
        acc += hA[i] * blA[(size_t)i * HH + j] + hB[i] * blB[(size_t)i * HH + j];

    float v = tanhf(acc) * out_w[j];
#pragma unroll
    for (int off = 16; off; off >>= 1) v += __shfl_xor_sync(0xffffffffu, v, off);
    if ((j & 31) == 0) red[j >> 5] = v;
    __syncthreads();
    if (j < 16) {
        float r = red[j];
#pragma unroll
        for (int off = 8; off; off >>= 1) r += __shfl_xor_sync(0x0000ffffu, r, off);
        if (j == 0) out[0] = 1.f / (1.f + expf(-(r + out_b[0])));
    }
}

// ---------------- launch ----------------------------------------------------------
extern "C" void kernel_launch(void* const* d_in, const int* in_sizes, int n_in,
                              void* d_out, int out_size)
{
    (void)in_sizes; (void)n_in; (void)out_size;
    const int*   sentA = (const int*)d_in[0];
    const int*   sentB = (const int*)d_in[1];
    const float* emb   = (const float*)d_in[3];
    const float* w_ih  = (const float*)d_in[4];
    const float* w_hh  = (const float*)d_in[5];
    const float* b_ih  = (const float*)d_in[6];
    const float* b_hh  = (const float*)d_in[7];
    const float* bi_w  = (const float*)d_in[8];
    const float* bi_b  = (const float*)d_in[9];
    const float* blA   = (const float*)d_in[10];
    const float* blB   = (const float*)d_in[11];
    const float* bl_b  = (const float*)d_in[12];
    const float* out_w = (const float*)d_in[13];
    const float* out_b = (const float*)d_in[14];
    float* out = (float*)d_out;

    gemm_gx_kernel<<<dim3(32, 64, 2), 256>>>(sentA, sentB, emb, w_ih, b_ih, b_hh);

    // dynamic smem sizes: w_sm + h_s + gates + stage + bars
    auto smem_for = [](int csz) {
        int upc = HH / csz, rows = 4 * upc;
        return (int)((8 * 12 * HH + 4 * HH + 2 * rows + 2 * upc) * sizeof(float)) + 16;
    };
    const int smem16 = smem_for(16);
    const int smem8  = smem_for(8);

    cudaFuncSetAttribute(lstm_cluster_kernel<16>,
                         cudaFuncAttributeNonPortableClusterSizeAllowed, 1);
    cudaFuncSetAttribute(lstm_cluster_kernel<16>,
                         cudaFuncAttributeMaxDynamicSharedMemorySize, smem16);
    cudaFuncSetAttribute(lstm_cluster_kernel<8>,
                         cudaFuncAttributeMaxDynamicSharedMemorySize, smem8);

    cudaLaunchConfig_t cfg = {};
    cfg.blockDim = dim3(256, 1, 1);
    cfg.stream = 0;
    cudaLaunchAttribute attr[1];
    attr[0].id = cudaLaunchAttributeClusterDimension;
    cfg.attrs = attr;
    cfg.numAttrs = 1;

    cfg.gridDim = dim3(2 * 16, 1, 1);
    cfg.dynamicSmemBytes = smem16;
    attr[0].val.clusterDim.x = 16; attr[0].val.clusterDim.y = 1; attr[0].val.clusterDim.z = 1;

    int nclusters = 0;
    cudaError_t e = cudaOccupancyMaxActiveClusters(&nclusters, lstm_cluster_kernel<16>, &cfg);
    if (e == cudaSuccess && nclusters >= 1) {
        cudaLaunchKernelEx(&cfg, lstm_cluster_kernel<16>, w_hh);
    } else {
        (void)cudaGetLastError();
        cfg.gridDim = dim3(2 * 8, 1, 1);
        cfg.dynamicSmemBytes = smem8;
        attr[0].val.clusterDim.x = 8;
        cudaLaunchKernelEx(&cfg, lstm_cluster_kernel<8>, w_hh);
    }

    head_kernel<<<1, 512>>>(bi_w, bi_b, blA, blB, bl_b, out_w, out_b, out);
}